// round 1
// baseline (speedup 1.0000x reference)
#include <cuda_runtime.h>
#include <cstdint>
#include <cstddef>

typedef unsigned long long ull;

#define NB 8192
#define NT 2048
#define NH 51

// ---------------- shared memory layout (bytes) ----------------
// 3 weight matrices, each stored as Wif [26][52] float4 then Wgo [26][52] float4
//   float4 at (kk, j) = { w_gA(2kk), w_gA(2kk+1), w_gB(2kk), w_gB(2kk+1) }
#define MATF   10816            // floats per matrix (2*26*52*4)
#define MATB   43264            // bytes per matrix
#define O_W    0
#define O_H1   129792           // 8 groups * [2][26][8] ull  (26624 B)
#define O_H2   156416           // same                        (26624 B)
#define O_BS1  183040           // [4][64] float (1024 B)
#define O_BS2  184064           // [4][64] float (1024 B)
#define O_WL   185088           // 52 floats = 26 f32x2 pairs (208 B)
#define SMEM_TOTAL 185344

__device__ __forceinline__ ull ffma2(ull a, ull b, ull c){
    ull d;
    asm("fma.rn.f32x2 %0, %1, %2, %3;" : "=l"(d) : "l"(a), "l"(b), "l"(c));
    return d;
}
__device__ __forceinline__ float lo2(ull a){ return __uint_as_float((unsigned)a); }
__device__ __forceinline__ float hi2(ull a){ return __uint_as_float((unsigned)(a >> 32)); }

__device__ __forceinline__ float fast_sig(float x){
    float e = __expf(-x);             // MUFU.EX2 based
    float r;
    asm("rcp.approx.f32 %0, %1;" : "=f"(r) : "f"(1.0f + e));
    return r;
}
__device__ __forceinline__ float fast_tanh(float x){
    return fmaf(2.0f, fast_sig(x + x), -1.0f);
}
__device__ __forceinline__ void gbar(int id){
    asm volatile("bar.sync %0, %1;" :: "r"(id), "r"(64) : "memory");
}

// stage one [4H, H] matrix into packed Wif/Wgo shared layout
__device__ __forceinline__ void stage_mat(const float* __restrict__ S, float* D, int tid){
    for (int idx = tid; idx < MATF; idx += 512){
        int half = idx / 5408;          // 0 -> gates (i,f), 1 -> gates (g,o)
        int rem  = idx - half*5408;
        int kk   = rem / 208;
        int r    = rem - kk*208;
        int j    = r >> 2;
        int q    = r & 3;
        int gate = half*2 + (q >> 1);
        int k    = 2*kk + (q & 1);
        float v = 0.0f;
        if (j < NH && k < NH) v = S[(gate*NH + j)*NH + k];
        D[idx] = v;
    }
}

__global__ void __launch_bounds__(512, 1)
lstm_kernel(const float* __restrict__ input,
            const float* __restrict__ Wih1, const float* __restrict__ Whh1,
            const float* __restrict__ bih1, const float* __restrict__ bhh1,
            const float* __restrict__ Wih2, const float* __restrict__ Whh2,
            const float* __restrict__ bih2, const float* __restrict__ bhh2,
            const float* __restrict__ Wlin, const float* __restrict__ blin,
            float* __restrict__ out)
{
    extern __shared__ char smem[];
    const int tid = threadIdx.x;

    // ---------------- stage weights / biases, zero h buffers ----------------
    stage_mat(Whh1, (float*)(smem + 0*MATB), tid);
    stage_mat(Wih2, (float*)(smem + 1*MATB), tid);
    stage_mat(Whh2, (float*)(smem + 2*MATB), tid);
    {
        float* bs1 = (float*)(smem + O_BS1);
        float* bs2 = (float*)(smem + O_BS2);
        for (int idx = tid; idx < 256; idx += 512){
            int g = idx >> 6, j = idx & 63;
            float v1 = 0.f, v2 = 0.f;
            if (j < NH){
                v1 = bih1[g*NH + j] + bhh1[g*NH + j];
                v2 = bih2[g*NH + j] + bhh2[g*NH + j];
            }
            bs1[idx] = v1; bs2[idx] = v2;
        }
        float* wl = (float*)(smem + O_WL);
        for (int idx = tid; idx < 52; idx += 512) wl[idx] = (idx < NH) ? Wlin[idx] : 0.f;
        ull* hz = (ull*)(smem + O_H1);
        for (int idx = tid; idx < 6656; idx += 512) hz[idx] = 0ull;  // h1 + h2 buffers
    }
    __syncthreads();

    const int grp = tid >> 6;          // 8 groups of 64 threads
    const int u   = tid & 63;          // hidden unit (active if < 51)
    const int b0  = blockIdx.x * 64 + grp * 8;   // first batch element of this group
    const int bid = grp + 1;           // named barrier id

    typedef ull HBuf[26][8];
    HBuf* h1b = (HBuf*)(smem + O_H1 + grp*3328);   // [2][26][8] pairs {h_2k, h_2k+1} per elem
    HBuf* h2b = (HBuf*)(smem + O_H2 + grp*3328);

    const ulonglong2* Wif1  = (const ulonglong2*)(smem + 0*MATB);
    const ulonglong2* Wgo1  = (const ulonglong2*)(smem + 0*MATB + 21632);
    const ulonglong2* Wif2i = (const ulonglong2*)(smem + 1*MATB);
    const ulonglong2* Wgo2i = (const ulonglong2*)(smem + 1*MATB + 21632);
    const ulonglong2* Wif2h = (const ulonglong2*)(smem + 2*MATB);
    const ulonglong2* Wgo2h = (const ulonglong2*)(smem + 2*MATB + 21632);
    const float* bs1 = (const float*)(smem + O_BS1);
    const float* bs2 = (const float*)(smem + O_BS2);
    const ull*   wlp = (const ull*)(smem + O_WL);

    float wx0 = 0.f, wx1 = 0.f, wx2 = 0.f, wx3 = 0.f;
    if (u < NH){
        wx0 = Wih1[0*NH + u]; wx1 = Wih1[1*NH + u];
        wx2 = Wih1[2*NH + u]; wx3 = Wih1[3*NH + u];
    }
    const float blin0 = blin[0];

    float c1[8], c2[8];
    #pragma unroll
    for (int e = 0; e < 8; e++){ c1[e] = 0.f; c2[e] = 0.f; }

    #pragma unroll 1
    for (int t = 0; t < NT; t++){
        const int cur = t & 1, nxt = cur ^ 1;

        if (u < NH){
            float x[8];
            #pragma unroll
            for (int e = 0; e < 8; e++)
                x[e] = input[(size_t)(b0 + e)*NT + t];

            // ---------------- layer 1 recurrent matvec ----------------
            ull a0[8], a1[8], a2[8], a3[8];
            #pragma unroll
            for (int e = 0; e < 8; e++){ a0[e]=0ull; a1[e]=0ull; a2[e]=0ull; a3[e]=0ull; }

            #pragma unroll 1
            for (int kk = 0; kk < 26; kk++){
                ulonglong2 wif = Wif1[kk*52 + u];
                ulonglong2 wgo = Wgo1[kk*52 + u];
                const ull* hr = h1b[cur][kk];
                #pragma unroll
                for (int p = 0; p < 4; p++){
                    ulonglong2 hp = *(const ulonglong2*)(hr + 2*p);
                    a0[2*p]   = ffma2(hp.x, wif.x, a0[2*p]);
                    a1[2*p]   = ffma2(hp.x, wif.y, a1[2*p]);
                    a2[2*p]   = ffma2(hp.x, wgo.x, a2[2*p]);
                    a3[2*p]   = ffma2(hp.x, wgo.y, a3[2*p]);
                    a0[2*p+1] = ffma2(hp.y, wif.x, a0[2*p+1]);
                    a1[2*p+1] = ffma2(hp.y, wif.y, a1[2*p+1]);
                    a2[2*p+1] = ffma2(hp.y, wgo.x, a2[2*p+1]);
                    a3[2*p+1] = ffma2(hp.y, wgo.y, a3[2*p+1]);
                }
            }
            {
                float bi = bs1[0*64+u], bf = bs1[1*64+u], bg = bs1[2*64+u], bo = bs1[3*64+u];
                float* hw = (float*)&h1b[nxt][u >> 1][0];
                const int hofs = (u & 1);
                #pragma unroll
                for (int e = 0; e < 8; e++){
                    float gi = lo2(a0[e]) + hi2(a0[e]) + fmaf(x[e], wx0, bi);
                    float gf = lo2(a1[e]) + hi2(a1[e]) + fmaf(x[e], wx1, bf);
                    float gg = lo2(a2[e]) + hi2(a2[e]) + fmaf(x[e], wx2, bg);
                    float go = lo2(a3[e]) + hi2(a3[e]) + fmaf(x[e], wx3, bo);
                    float cn = fast_sig(gf)*c1[e] + fast_sig(gi)*fast_tanh(gg);
                    c1[e] = cn;
                    hw[2*e + hofs] = fast_sig(go)*fast_tanh(cn);
                }
            }
        }
        gbar(bid);   // h1(new) visible to whole group

        if (u < NH){
            // ---------------- layer 2: W_ih2 * h1(new) + W_hh2 * h2(old) ----------------
            ull a0[8], a1[8], a2[8], a3[8];
            #pragma unroll
            for (int e = 0; e < 8; e++){ a0[e]=0ull; a1[e]=0ull; a2[e]=0ull; a3[e]=0ull; }

            #pragma unroll 1
            for (int kk = 0; kk < 26; kk++){
                ulonglong2 wia = Wif2i[kk*52 + u];
                ulonglong2 wga = Wgo2i[kk*52 + u];
                ulonglong2 wib = Wif2h[kk*52 + u];
                ulonglong2 wgb = Wgo2h[kk*52 + u];
                const ull* h1r = h1b[nxt][kk];
                const ull* h2r = h2b[cur][kk];
                #pragma unroll
                for (int p = 0; p < 4; p++){
                    ulonglong2 hp = *(const ulonglong2*)(h1r + 2*p);
                    ulonglong2 qp = *(const ulonglong2*)(h2r + 2*p);
                    a0[2*p]   = ffma2(hp.x, wia.x, a0[2*p]);
                    a1[2*p]   = ffma2(hp.x, wia.y, a1[2*p]);
                    a2[2*p]   = ffma2(hp.x, wga.x, a2[2*p]);
                    a3[2*p]   = ffma2(hp.x, wga.y, a3[2*p]);
                    a0[2*p]   = ffma2(qp.x, wib.x, a0[2*p]);
                    a1[2*p]   = ffma2(qp.x, wib.y, a1[2*p]);
                    a2[2*p]   = ffma2(qp.x, wgb.x, a2[2*p]);
                    a3[2*p]   = ffma2(qp.x, wgb.y, a3[2*p]);
                    a0[2*p+1] = ffma2(hp.y, wia.x, a0[2*p+1]);
                    a1[2*p+1] = ffma2(hp.y, wia.y, a1[2*p+1]);
                    a2[2*p+1] = ffma2(hp.y, wga.x, a2[2*p+1]);
                    a3[2*p+1] = ffma2(hp.y, wga.y, a3[2*p+1]);
                    a0[2*p+1] = ffma2(qp.y, wib.x, a0[2*p+1]);
                    a1[2*p+1] = ffma2(qp.y, wib.y, a1[2*p+1]);
                    a2[2*p+1] = ffma2(qp.y, wgb.x, a2[2*p+1]);
                    a3[2*p+1] = ffma2(qp.y, wgb.y, a3[2*p+1]);
                }
            }
            {
                float bi = bs2[0*64+u], bf = bs2[1*64+u], bg = bs2[2*64+u], bo = bs2[3*64+u];
                float* hw = (float*)&h2b[nxt][u >> 1][0];
                const int hofs = (u & 1);
                #pragma unroll
                for (int e = 0; e < 8; e++){
                    float gi = lo2(a0[e]) + hi2(a0[e]) + bi;
                    float gf = lo2(a1[e]) + hi2(a1[e]) + bf;
                    float gg = lo2(a2[e]) + hi2(a2[e]) + bg;
                    float go = lo2(a3[e]) + hi2(a3[e]) + bo;
                    float cn = fast_sig(gf)*c2[e] + fast_sig(gi)*fast_tanh(gg);
                    c2[e] = cn;
                    hw[2*e + hofs] = fast_sig(go)*fast_tanh(cn);
                }
            }
        }
        gbar(bid);   // h2(new) visible

        // ---------------- output projection: one thread per element ----------------
        if (u < 8){
            ull p = 0ull;
            #pragma unroll 1
            for (int kk = 0; kk < 26; kk++)
                p = ffma2(h2b[nxt][kk][u], wlp[kk], p);
            out[(size_t)(b0 + u)*NT + t] = lo2(p) + hi2(p) + blin0;
        }
    }
}

extern "C" void kernel_launch(void* const* d_in, const int* in_sizes, int n_in,
                              void* d_out, int out_size)
{
    (void)in_sizes; (void)n_in; (void)out_size;
    const float* input = (const float*)d_in[0];
    const float* Wih1  = (const float*)d_in[1];
    const float* Whh1  = (const float*)d_in[2];
    const float* bih1  = (const float*)d_in[3];
    const float* bhh1  = (const float*)d_in[4];
    const float* Wih2  = (const float*)d_in[5];
    const float* Whh2  = (const float*)d_in[6];
    const float* bih2  = (const float*)d_in[7];
    const float* bhh2  = (const float*)d_in[8];
    const float* Wlin  = (const float*)d_in[9];
    const float* blin  = (const float*)d_in[10];
    float* out = (float*)d_out;

    cudaFuncSetAttribute(lstm_kernel, cudaFuncAttributeMaxDynamicSharedMemorySize, SMEM_TOTAL);
    lstm_kernel<<<128, 512, SMEM_TOTAL>>>(input, Wih1, Whh1, bih1, bhh1,
                                          Wih2, Whh2, bih2, bhh2, Wlin, blin, out);
}

// round 2
// speedup vs baseline: 1.0629x; 1.0629x over previous
#include <cuda_runtime.h>
#include <cstdint>
#include <cstddef>

typedef unsigned long long ull;

#define NB 8192
#define NT 2048
#define NH 51

// ---------------- shared memory layout (bytes) ----------------
// 3 weight matrices, each stored as Wif [26][52] float4 then Wgo [26][52] float4
//   float4 at (kk, j) = { w_gA(2kk), w_gA(2kk+1), w_gB(2kk), w_gB(2kk+1) }
#define MATF   10816            // floats per matrix (2*26*52*4)
#define MATB   43264            // bytes per matrix
#define O_W    0
#define O_H1   129792           // 8 groups * [2][26][8] ull  (26624 B)
#define O_H2   156416           // same                        (26624 B)
#define O_BS1  183040           // [4][64] float (1024 B)
#define O_BS2  184064           // [4][64] float (1024 B)
#define O_WL   185088           // 52 floats = 26 f32x2 pairs (208 B)
#define SMEM_TOTAL 185344

__device__ __forceinline__ ull ffma2(ull a, ull b, ull c){
    ull d;
    asm("fma.rn.f32x2 %0, %1, %2, %3;" : "=l"(d) : "l"(a), "l"(b), "l"(c));
    return d;
}
__device__ __forceinline__ float lo2(ull a){ return __uint_as_float((unsigned)a); }
__device__ __forceinline__ float hi2(ull a){ return __uint_as_float((unsigned)(a >> 32)); }

__device__ __forceinline__ float fast_sig(float x){
    float e = __expf(-x);             // MUFU.EX2 based
    float r;
    asm("rcp.approx.f32 %0, %1;" : "=f"(r) : "f"(1.0f + e));
    return r;
}
__device__ __forceinline__ float fast_tanh(float x){
    return fmaf(2.0f, fast_sig(x + x), -1.0f);
}
__device__ __forceinline__ void gbar(int id){
    asm volatile("bar.sync %0, %1;" :: "r"(id), "r"(64) : "memory");
}

// stage one [4H, H] matrix into packed Wif/Wgo shared layout
__device__ __forceinline__ void stage_mat(const float* __restrict__ S, float* D, int tid){
    for (int idx = tid; idx < MATF; idx += 512){
        int half = idx / 5408;          // 0 -> gates (i,f), 1 -> gates (g,o)
        int rem  = idx - half*5408;
        int kk   = rem / 208;
        int r    = rem - kk*208;
        int j    = r >> 2;
        int q    = r & 3;
        int gate = half*2 + (q >> 1);
        int k    = 2*kk + (q & 1);
        float v = 0.0f;
        if (j < NH && k < NH) v = S[(gate*NH + j)*NH + k];
        D[idx] = v;
    }
}

__global__ void __launch_bounds__(512, 1)
lstm_kernel(const float* __restrict__ input,
            const float* __restrict__ Wih1, const float* __restrict__ Whh1,
            const float* __restrict__ bih1, const float* __restrict__ bhh1,
            const float* __restrict__ Wih2, const float* __restrict__ Whh2,
            const float* __restrict__ bih2, const float* __restrict__ bhh2,
            const float* __restrict__ Wlin, const float* __restrict__ blin,
            float* __restrict__ out)
{
    extern __shared__ char smem[];
    const int tid = threadIdx.x;

    // ---------------- stage weights / biases, zero h buffers ----------------
    stage_mat(Whh1, (float*)(smem + 0*MATB), tid);
    stage_mat(Wih2, (float*)(smem + 1*MATB), tid);
    stage_mat(Whh2, (float*)(smem + 2*MATB), tid);
    {
        float* bs1 = (float*)(smem + O_BS1);
        float* bs2 = (float*)(smem + O_BS2);
        for (int idx = tid; idx < 256; idx += 512){
            int g = idx >> 6, j = idx & 63;
            float v1 = 0.f, v2 = 0.f;
            if (j < NH){
                v1 = bih1[g*NH + j] + bhh1[g*NH + j];
                v2 = bih2[g*NH + j] + bhh2[g*NH + j];
            }
            bs1[idx] = v1; bs2[idx] = v2;
        }
        float* wl = (float*)(smem + O_WL);
        for (int idx = tid; idx < 52; idx += 512) wl[idx] = (idx < NH) ? Wlin[idx] : 0.f;
        ull* hz = (ull*)(smem + O_H1);
        for (int idx = tid; idx < 6656; idx += 512) hz[idx] = 0ull;  // h1 + h2 buffers
    }
    __syncthreads();

    const int grp = tid >> 6;          // 8 groups of 64 threads
    const int u   = tid & 63;          // hidden unit (active if < 51)
    const int b0  = blockIdx.x * 64 + grp * 8;   // first batch element of this group
    const int bid = grp + 1;           // named barrier id

    typedef ull HBuf[26][8];
    HBuf* h1b = (HBuf*)(smem + O_H1 + grp*3328);   // [2][26][8] pairs {h_2k, h_2k+1} per elem
    HBuf* h2b = (HBuf*)(smem + O_H2 + grp*3328);

    const ulonglong2* Wif1  = (const ulonglong2*)(smem + 0*MATB);
    const ulonglong2* Wgo1  = (const ulonglong2*)(smem + 0*MATB + 21632);
    const ulonglong2* Wif2i = (const ulonglong2*)(smem + 1*MATB);
    const ulonglong2* Wgo2i = (const ulonglong2*)(smem + 1*MATB + 21632);
    const ulonglong2* Wif2h = (const ulonglong2*)(smem + 2*MATB);
    const ulonglong2* Wgo2h = (const ulonglong2*)(smem + 2*MATB + 21632);
    const float* bs1 = (const float*)(smem + O_BS1);
    const float* bs2 = (const float*)(smem + O_BS2);
    const ull*   wlp = (const ull*)(smem + O_WL);

    float wx0 = 0.f, wx1 = 0.f, wx2 = 0.f, wx3 = 0.f;
    if (u < NH){
        wx0 = Wih1[0*NH + u]; wx1 = Wih1[1*NH + u];
        wx2 = Wih1[2*NH + u]; wx3 = Wih1[3*NH + u];
    }
    const float blin0 = blin[0];

    float c1[8], c2[8];
    #pragma unroll
    for (int e = 0; e < 8; e++){ c1[e] = 0.f; c2[e] = 0.f; }

    #pragma unroll 1
    for (int t = 0; t < NT; t++){
        const int cur = t & 1, nxt = cur ^ 1;

        if (u < NH){
            float x[8];
            #pragma unroll
            for (int e = 0; e < 8; e++)
                x[e] = input[(size_t)(b0 + e)*NT + t];

            // ---------------- layer 1 recurrent matvec ----------------
            ull a0[8], a1[8], a2[8], a3[8];
            #pragma unroll
            for (int e = 0; e < 8; e++){ a0[e]=0ull; a1[e]=0ull; a2[e]=0ull; a3[e]=0ull; }

            #pragma unroll 1
            for (int kk = 0; kk < 26; kk++){
                ulonglong2 wif = Wif1[kk*52 + u];
                ulonglong2 wgo = Wgo1[kk*52 + u];
                const ull* hr = h1b[cur][kk];
                #pragma unroll
                for (int p = 0; p < 4; p++){
                    ulonglong2 hp = *(const ulonglong2*)(hr + 2*p);
                    a0[2*p]   = ffma2(hp.x, wif.x, a0[2*p]);
                    a1[2*p]   = ffma2(hp.x, wif.y, a1[2*p]);
                    a2[2*p]   = ffma2(hp.x, wgo.x, a2[2*p]);
                    a3[2*p]   = ffma2(hp.x, wgo.y, a3[2*p]);
                    a0[2*p+1] = ffma2(hp.y, wif.x, a0[2*p+1]);
                    a1[2*p+1] = ffma2(hp.y, wif.y, a1[2*p+1]);
                    a2[2*p+1] = ffma2(hp.y, wgo.x, a2[2*p+1]);
                    a3[2*p+1] = ffma2(hp.y, wgo.y, a3[2*p+1]);
                }
            }
            {
                float bi = bs1[0*64+u], bf = bs1[1*64+u], bg = bs1[2*64+u], bo = bs1[3*64+u];
                float* hw = (float*)&h1b[nxt][u >> 1][0];
                const int hofs = (u & 1);
                #pragma unroll
                for (int e = 0; e < 8; e++){
                    float gi = lo2(a0[e]) + hi2(a0[e]) + fmaf(x[e], wx0, bi);
                    float gf = lo2(a1[e]) + hi2(a1[e]) + fmaf(x[e], wx1, bf);
                    float gg = lo2(a2[e]) + hi2(a2[e]) + fmaf(x[e], wx2, bg);
                    float go = lo2(a3[e]) + hi2(a3[e]) + fmaf(x[e], wx3, bo);
                    float cn = fast_sig(gf)*c1[e] + fast_sig(gi)*fast_tanh(gg);
                    c1[e] = cn;
                    hw[2*e + hofs] = fast_sig(go)*fast_tanh(cn);
                }
            }
        }
        gbar(bid);   // h1(new) visible to whole group

        if (u < NH){
            // ---------------- layer 2: W_ih2 * h1(new) + W_hh2 * h2(old) ----------------
            ull a0[8], a1[8], a2[8], a3[8];
            #pragma unroll
            for (int e = 0; e < 8; e++){ a0[e]=0ull; a1[e]=0ull; a2[e]=0ull; a3[e]=0ull; }

            #pragma unroll 1
            for (int kk = 0; kk < 26; kk++){
                ulonglong2 wia = Wif2i[kk*52 + u];
                ulonglong2 wga = Wgo2i[kk*52 + u];
                ulonglong2 wib = Wif2h[kk*52 + u];
                ulonglong2 wgb = Wgo2h[kk*52 + u];
                const ull* h1r = h1b[nxt][kk];
                const ull* h2r = h2b[cur][kk];
                #pragma unroll
                for (int p = 0; p < 4; p++){
                    ulonglong2 hp = *(const ulonglong2*)(h1r + 2*p);
                    ulonglong2 qp = *(const ulonglong2*)(h2r + 2*p);
                    a0[2*p]   = ffma2(hp.x, wia.x, a0[2*p]);
                    a1[2*p]   = ffma2(hp.x, wia.y, a1[2*p]);
                    a2[2*p]   = ffma2(hp.x, wga.x, a2[2*p]);
                    a3[2*p]   = ffma2(hp.x, wga.y, a3[2*p]);
                    a0[2*p]   = ffma2(qp.x, wib.x, a0[2*p]);
                    a1[2*p]   = ffma2(qp.x, wib.y, a1[2*p]);
                    a2[2*p]   = ffma2(qp.x, wgb.x, a2[2*p]);
                    a3[2*p]   = ffma2(qp.x, wgb.y, a3[2*p]);
                    a0[2*p+1] = ffma2(hp.y, wia.x, a0[2*p+1]);
                    a1[2*p+1] = ffma2(hp.y, wia.y, a1[2*p+1]);
                    a2[2*p+1] = ffma2(hp.y, wga.x, a2[2*p+1]);
                    a3[2*p+1] = ffma2(hp.y, wga.y, a3[2*p+1]);
                    a0[2*p+1] = ffma2(qp.y, wib.x, a0[2*p+1]);
                    a1[2*p+1] = ffma2(qp.y, wib.y, a1[2*p+1]);
                    a2[2*p+1] = ffma2(qp.y, wgb.x, a2[2*p+1]);
                    a3[2*p+1] = ffma2(qp.y, wgb.y, a3[2*p+1]);
                }
            }
            {
                float bi = bs2[0*64+u], bf = bs2[1*64+u], bg = bs2[2*64+u], bo = bs2[3*64+u];
                float* hw = (float*)&h2b[nxt][u >> 1][0];
                const int hofs = (u & 1);
                #pragma unroll
                for (int e = 0; e < 8; e++){
                    float gi = lo2(a0[e]) + hi2(a0[e]) + bi;
                    float gf = lo2(a1[e]) + hi2(a1[e]) + bf;
                    float gg = lo2(a2[e]) + hi2(a2[e]) + bg;
                    float go = lo2(a3[e]) + hi2(a3[e]) + bo;
                    float cn = fast_sig(gf)*c2[e] + fast_sig(gi)*fast_tanh(gg);
                    c2[e] = cn;
                    hw[2*e + hofs] = fast_sig(go)*fast_tanh(cn);
                }
            }
        }
        gbar(bid);   // h2(new) visible

        // ---------------- output projection: one thread per element ----------------
        if (u < 8){
            ull p = 0ull;
            #pragma unroll 1
            for (int kk = 0; kk < 26; kk++)
                p = ffma2(h2b[nxt][kk][u], wlp[kk], p);
            out[(size_t)(b0 + u)*NT + t] = lo2(p) + hi2(p) + blin0;
        }
    }
}

extern "C" void kernel_launch(void* const* d_in, const int* in_sizes, int n_in,
                              void* d_out, int out_size)
{
    (void)in_sizes; (void)n_in; (void)out_size;
    const float* input = (const float*)d_in[0];
    const float* Wih1  = (const float*)d_in[1];
    const float* Whh1  = (const float*)d_in[2];
    const float* bih1  = (const float*)d_in[3];
    const float* bhh1  = (const float*)d_in[4];
    const float* Wih2  = (const float*)d_in[5];
    const float* Whh2  = (const float*)d_in[6];
    const float* bih2  = (const float*)d_in[7];
    const float* bhh2  = (const float*)d_in[8];
    const float* Wlin  = (const float*)d_in[9];
    const float* blin  = (const float*)d_in[10];
    float* out = (float*)d_out;

    cudaFuncSetAttribute(lstm_kernel, cudaFuncAttributeMaxDynamicSharedMemorySize, SMEM_TOTAL);
    lstm_kernel<<<128, 512, SMEM_TOTAL>>>(input, Wih1, Whh1, bih1, bhh1,
                                          Wih2, Whh2, bih2, bhh2, Wlin, blin, out);
}